// round 6
// baseline (speedup 1.0000x reference)
#include <cuda_runtime.h>
#include <cstdint>
#include <math.h>

typedef unsigned long long ull;

// Problem constants
#define B_    32
#define L_    2048
#define I_    256
#define H_    512
#define HX    768      // H + I
#define N3    1536     // 3*H (z | r | w)
#define NCG   16       // CTAs per cluster (column groups)
#define NBG   8        // clusters (batch groups)
#define BPG   4        // batches per group
#define CPG   32       // gate columns per CTA per gate
#define NTHR  256

// ---------------- device scratch ----------------
__device__ float g_X[(size_t)L_ * B_ * N3];   // precomputed x-contributions

// ---------------- smem layout (byte offsets) ----------------
#define WR_B   0            // 32 x 512 f32
#define WZ_B   65536
#define WW_B   131072
#define HB0_B  196608       // h buffer, parity 0: 4 x 512 f32
#define HB1_B  204800       // h buffer, parity 1
#define RH0_B  212992       // r*h buffer, parity 0
#define RH1_B  221184       // r*h buffer, parity 1
#define SCR_B  229376       // scratch: 128 f32 (this CTA's block)
#define RBAR_B 229888       // rh mbarrier
#define HBAR_B 229896       // h mbarrier
#define SMEM_BYTES 229952

// ---------------- asm helpers ----------------
__device__ __forceinline__ uint32_t smem_u32(const void* p) {
    uint32_t a;
    asm("{ .reg .u64 t; cvta.to.shared.u64 t, %1; cvt.u32.u64 %0, t; }" : "=r"(a) : "l"(p));
    return a;
}
__device__ __forceinline__ ull lds64(uint32_t a) {
    ull v;
    asm volatile("ld.shared.b64 %0, [%1];" : "=l"(v) : "r"(a));
    return v;
}
__device__ __forceinline__ float lds32(uint32_t a) {
    float v;
    asm volatile("ld.shared.f32 %0, [%1];" : "=f"(v) : "r"(a));
    return v;
}
__device__ __forceinline__ void sts32(uint32_t a, float v) {
    asm volatile("st.shared.f32 [%0], %1;" :: "r"(a), "f"(v) : "memory");
}
__device__ __forceinline__ void fma2(ull& acc, ull a, ull b) {
    asm volatile("fma.rn.f32x2 %0, %1, %2, %0;" : "+l"(acc) : "l"(a), "l"(b));
}
__device__ __forceinline__ float sum2(ull v) {
    float lo, hi;
    asm("mov.b64 {%0, %1}, %2;" : "=f"(lo), "=f"(hi) : "l"(v));
    return lo + hi;
}
__device__ __forceinline__ uint32_t mapa_u32(uint32_t laddr, uint32_t rank) {
    uint32_t r;
    asm("mapa.shared::cluster.u32 %0, %1, %2;" : "=r"(r) : "r"(laddr), "r"(rank));
    return r;
}

#define MBARRIER_INIT16(addr) \
    asm volatile("mbarrier.init.shared.b64 [%0], 16;" :: "r"(addr) : "memory")

#define MBAR_WAIT_CLUSTER(addr, par) do {                                        \
    asm volatile("{\n\t"                                                         \
        ".reg .pred P;\n\t"                                                      \
        "W_%=:\n\t"                                                              \
        "mbarrier.try_wait.parity.acquire.cluster.shared::cta.b64 P, [%0], %1, 0x989680;\n\t" \
        "@P bra.uni D_%=;\n\t"                                                   \
        "bra.uni W_%=;\n\t"                                                      \
        "D_%=:\n\t"                                                              \
        "}" :: "r"(addr), "r"(par) : "memory");                                  \
} while (0)

#define CLUSTER_SYNC() do { \
    asm volatile("barrier.cluster.arrive.aligned;" ::: "memory"); \
    asm volatile("barrier.cluster.wait.aligned;"   ::: "memory"); \
} while (0)

// push this CTA's 128-float scratch block to peer `rank`'s buffer (local byte
// offset buf_local within each CTA's smem), then arrive on the peer's mbarrier.
__device__ __forceinline__ void push_block(uint32_t sb, uint32_t buf_local,
                                           uint32_t bar_local, int rank, int c0) {
    uint32_t dbase = mapa_u32(sb + buf_local, (uint32_t)rank);
    uint32_t dbar  = mapa_u32(sb + bar_local, (uint32_t)rank);
#pragma unroll
    for (int j = 0; j < 64; j++) {                  // 64 x 8B = 512B
        int b = j >> 4, p2 = j & 15;                // batch, float-pair index
        ull v = lds64(sb + SCR_B + (uint32_t)j * 8u);
        uint32_t daddr = dbase + (uint32_t)(b * 2048 + (c0 + p2 * 2) * 4);
        asm volatile("st.shared::cluster.b64 [%0], %1;" :: "r"(daddr), "l"(v) : "memory");
    }
    asm volatile("mbarrier.arrive.release.cluster.shared::cluster.b64 _, [%0];"
                 :: "r"(dbar) : "memory");
}

// ---------------- warp reduction: 16 chains over 32 lanes ----------------
// After return: thread pair (2l, 2l+1) holds chain o = (lane>>1)&15 in a[0].
__device__ __forceinline__ void reduce16(float a[16], int lane) {
#pragma unroll
    for (int o = 0; o < 8; o++) {
        bool hi = (lane & 16);
        float send = hi ? a[o] : a[o + 8];
        float keep = hi ? a[o + 8] : a[o];
        a[o] = keep + __shfl_xor_sync(0xffffffffu, send, 16);
    }
#pragma unroll
    for (int o = 0; o < 4; o++) {
        bool hi = (lane & 8);
        float send = hi ? a[o] : a[o + 4];
        float keep = hi ? a[o + 4] : a[o];
        a[o] = keep + __shfl_xor_sync(0xffffffffu, send, 8);
    }
#pragma unroll
    for (int o = 0; o < 2; o++) {
        bool hi = (lane & 4);
        float send = hi ? a[o] : a[o + 2];
        float keep = hi ? a[o + 2] : a[o];
        a[o] = keep + __shfl_xor_sync(0xffffffffu, send, 4);
    }
    {
        bool hi = (lane & 2);
        float send = hi ? a[0] : a[1];
        float keep = hi ? a[1] : a[0];
        a[0] = keep + __shfl_xor_sync(0xffffffffu, send, 2);
    }
    a[0] += __shfl_xor_sync(0xffffffffu, a[0], 1);
}

// ---------------- precompute GEMM: g_X = x . W[:,512:768]^T ----------------
__global__ void __launch_bounds__(256) precompute_x_kernel(
    const float* __restrict__ x,
    const float* __restrict__ Wz,
    const float* __restrict__ Wr,
    const float* __restrict__ Ww)
{
    __shared__ float As[16][132];
    __shared__ float Bs[16][132];

    const int m0 = blockIdx.y * 128;
    const int n0 = blockIdx.x * 128;
    const int tid = threadIdx.x;
    const int ty = tid >> 4;
    const int tx = tid & 15;

    float acc[8][8];
#pragma unroll
    for (int i = 0; i < 8; i++)
#pragma unroll
        for (int j = 0; j < 8; j++) acc[i][j] = 0.f;

    for (int k0 = 0; k0 < 256; k0 += 16) {
#pragma unroll
        for (int q = tid; q < 512; q += 256) {
            int r  = q >> 2;
            int kq = (q & 3) << 2;
            float4 v = *(const float4*)(x + (size_t)(m0 + r) * 256 + k0 + kq);
            As[kq + 0][r] = v.x; As[kq + 1][r] = v.y;
            As[kq + 2][r] = v.z; As[kq + 3][r] = v.w;
        }
#pragma unroll
        for (int q = tid; q < 512; q += 256) {
            int r  = q >> 2;
            int kq = (q & 3) << 2;
            int n  = n0 + r;
            const float* wrow;
            if (n < 512)        wrow = Wz + (size_t)n * HX;
            else if (n < 1024)  wrow = Wr + (size_t)(n - 512) * HX;
            else                wrow = Ww + (size_t)(n - 1024) * HX;
            float4 v = *(const float4*)(wrow + 512 + k0 + kq);
            Bs[kq + 0][r] = v.x; Bs[kq + 1][r] = v.y;
            Bs[kq + 2][r] = v.z; Bs[kq + 3][r] = v.w;
        }
        __syncthreads();
#pragma unroll
        for (int kk = 0; kk < 16; kk++) {
            float a[8], b[8];
#pragma unroll
            for (int i = 0; i < 8; i++) a[i] = As[kk][ty * 8 + i];
#pragma unroll
            for (int j = 0; j < 8; j++) b[j] = Bs[kk][tx * 8 + j];
#pragma unroll
            for (int i = 0; i < 8; i++)
#pragma unroll
                for (int j = 0; j < 8; j++) acc[i][j] += a[i] * b[j];
        }
        __syncthreads();
    }

#pragma unroll
    for (int i = 0; i < 8; i++) {
        int m = m0 + ty * 8 + i;
        int t = m & 2047;
        int b = m >> 11;
        size_t base = ((size_t)t * B_ + b) * N3 + n0 + tx * 8;
        *(float4*)&g_X[base + 0] = make_float4(acc[i][0], acc[i][1], acc[i][2], acc[i][3]);
        *(float4*)&g_X[base + 4] = make_float4(acc[i][4], acc[i][5], acc[i][6], acc[i][7]);
    }
}

// ---------------- clustered recurrent kernel ----------------
__global__ void __launch_bounds__(NTHR, 1) gru_cluster_kernel(
    const float* __restrict__ h0,
    const float* __restrict__ Wz,
    const float* __restrict__ Wr,
    const float* __restrict__ Ww,
    float* __restrict__ out)
{
    extern __shared__ float sm[];
    const uint32_t sb = smem_u32(sm);
    char* smc = (char*)sm;
    const int tid  = threadIdx.x;
    const int wg   = tid >> 5;
    const int lane = tid & 31;
    const int cg   = blockIdx.x;       // rank within cluster
    const int bg   = blockIdx.y;       // batch group
    const int b0   = bg * BPG;
    const int c0   = cg * CPG;

    // ---- cache weight h-parts: 3 x [32 rows x 512] ----
    for (int q = tid; q < 32 * 128; q += NTHR) {
        int row = q >> 7, f4 = q & 127;
        *(float4*)(smc + WR_B + row * 2048 + f4 * 16) = *(const float4*)(Wr + (size_t)(c0 + row) * HX + f4 * 4);
        *(float4*)(smc + WZ_B + row * 2048 + f4 * 16) = *(const float4*)(Wz + (size_t)(c0 + row) * HX + f4 * 4);
        *(float4*)(smc + WW_B + row * 2048 + f4 * 16) = *(const float4*)(Ww + (size_t)(c0 + row) * HX + f4 * 4);
    }
    // ---- mbarriers + h0 into buffer 0 ----
    if (tid == 0) {
        MBARRIER_INIT16(sb + RBAR_B);
        MBARRIER_INIT16(sb + HBAR_B);
    }
    for (int q = tid; q < 512; q += NTHR) {
        int b = q >> 7, f4 = q & 127;
        *(float4*)(smc + HB0_B + b * 2048 + f4 * 16) = __ldcg(((const float4*)(h0 + (size_t)(b0 + b) * H_)) + f4);
    }
    __syncthreads();
    CLUSTER_SYNC();    // mbarriers initialized cluster-wide before any arrival

    // output mapping: even lanes own output o = (lane>>1)&15 = c*4+b
    const int o   = (lane >> 1) & 15;
    const int oc  = o >> 2;              // col within warp's 4
    const int ob  = o & 3;               // batch within group
    const int colg = c0 + wg * 4 + oc;   // global gate column (0..511)
    const int coll = wg * 4 + oc;        // local column (0..31)
    const bool wr  = !(lane & 1);

    for (int t = 0; t < L_; t++) {
        const uint32_t hb_b = sb + ((t & 1) ? HB1_B : HB0_B);
        const uint32_t rh_b = sb + ((t & 1) ? RH1_B : RH0_B);
        const uint32_t hn_off = ((t & 1) ? HB0_B : HB1_B);   // next-h buffer

        // ---- wait for h(t) (pushed by peers at end of step t-1) ----
        if (t > 0) MBAR_WAIT_CLUSTER(sb + HBAR_B, (unsigned)((t - 1) & 1));

        // ---- prefetch x-contributions ----
        const size_t xbase = ((size_t)t * B_ + b0 + ob) * N3;
        float xz = __ldg(&g_X[xbase + colg]);
        float xr = __ldg(&g_X[xbase + 512 + colg]);
        float xw = __ldg(&g_X[xbase + 1024 + colg]);

        // ---- load h slice into registers (reused by r and z gates) ----
        ull hb[4][8];
#pragma unroll
        for (int b = 0; b < 4; b++)
#pragma unroll
            for (int i = 0; i < 8; i++)
                hb[b][i] = lds64(hb_b + (uint32_t)(b * 2048 + (i * 32 + lane) * 8));
        float hval = lds32(hb_b + (uint32_t)(ob * 2048 + colg * 4));

        // ================= r gate =================
        {
            ull acc[4][4];
#pragma unroll
            for (int c = 0; c < 4; c++)
#pragma unroll
                for (int b = 0; b < 4; b++) acc[c][b] = 0ull;

            const uint32_t wb = sb + WR_B + (uint32_t)((wg * 4) * 2048);
#pragma unroll
            for (int i = 0; i < 8; i++) {
                uint32_t off = (uint32_t)(i * 32 + lane) * 8u;
#pragma unroll
                for (int c = 0; c < 4; c++) {
                    ull wv = lds64(wb + c * 2048 + off);
                    fma2(acc[c][0], hb[0][i], wv);
                    fma2(acc[c][1], hb[1][i], wv);
                    fma2(acc[c][2], hb[2][i], wv);
                    fma2(acc[c][3], hb[3][i], wv);
                }
            }
            float a[16];
#pragma unroll
            for (int c = 0; c < 4; c++)
#pragma unroll
                for (int b = 0; b < 4; b++) a[c * 4 + b] = sum2(acc[c][b]);
            reduce16(a, lane);

            if (wr) {
                float r = 1.f / (1.f + __expf(-(a[0] + xr)));
                sts32(sb + SCR_B + (uint32_t)(ob * 32 + coll) * 4u, r * hval);
            }
        }
        __syncthreads();   // scratch complete

        // ---- push r*h block to all 16 peers (threads 0..15, one dest each) ----
        if (tid < NCG) {
            uint32_t dst_off = (t & 1) ? RH1_B : RH0_B;
            push_block(sb, dst_off, RBAR_B, tid, c0);
        }

        // ================= z gate (overlaps r*h exchange) =================
        float zv;
        {
            ull acc[4][4];
#pragma unroll
            for (int c = 0; c < 4; c++)
#pragma unroll
                for (int b = 0; b < 4; b++) acc[c][b] = 0ull;

            const uint32_t wb = sb + WZ_B + (uint32_t)((wg * 4) * 2048);
#pragma unroll
            for (int i = 0; i < 8; i++) {
                uint32_t off = (uint32_t)(i * 32 + lane) * 8u;
#pragma unroll
                for (int c = 0; c < 4; c++) {
                    ull wv = lds64(wb + c * 2048 + off);
                    fma2(acc[c][0], hb[0][i], wv);
                    fma2(acc[c][1], hb[1][i], wv);
                    fma2(acc[c][2], hb[2][i], wv);
                    fma2(acc[c][3], hb[3][i], wv);
                }
            }
            float a[16];
#pragma unroll
            for (int c = 0; c < 4; c++)
#pragma unroll
                for (int b = 0; b < 4; b++) a[c * 4 + b] = sum2(acc[c][b]);
            reduce16(a, lane);
            zv = 1.f / (1.f + __expf(-(a[0] + xz)));
        }

        // ---- wait for all peers' r*h ----
        MBAR_WAIT_CLUSTER(sb + RBAR_B, (unsigned)(t & 1));

        // ================= w gate (candidate) + blend =================
        {
            ull rb[4][8];
#pragma unroll
            for (int b = 0; b < 4; b++)
#pragma unroll
                for (int i = 0; i < 8; i++)
                    rb[b][i] = lds64(rh_b + (uint32_t)(b * 2048 + (i * 32 + lane) * 8));

            ull acc[4][4];
#pragma unroll
            for (int c = 0; c < 4; c++)
#pragma unroll
                for (int b = 0; b < 4; b++) acc[c][b] = 0ull;

            const uint32_t wb = sb + WW_B + (uint32_t)((wg * 4) * 2048);
#pragma unroll
            for (int i = 0; i < 8; i++) {
                uint32_t off = (uint32_t)(i * 32 + lane) * 8u;
#pragma unroll
                for (int c = 0; c < 4; c++) {
                    ull wv = lds64(wb + c * 2048 + off);
                    fma2(acc[c][0], rb[0][i], wv);
                    fma2(acc[c][1], rb[1][i], wv);
                    fma2(acc[c][2], rb[2][i], wv);
                    fma2(acc[c][3], rb[3][i], wv);
                }
            }
            float a[16];
#pragma unroll
            for (int c = 0; c < 4; c++)
#pragma unroll
                for (int b = 0; b < 4; b++) a[c * 4 + b] = sum2(acc[c][b]);
            reduce16(a, lane);

            if (wr) {
                float hh = tanhf(a[0] + xw);
                float hn = hval + zv * (hh - hval);
                __stcg(&out[((size_t)t * B_ + b0 + ob) * H_ + colg], hn);   // off critical path
                sts32(sb + SCR_B + (uint32_t)(ob * 32 + coll) * 4u, hn);
            }
        }
        __syncthreads();   // scratch complete (also ensures rh-push readers done)

        // ---- push h(t+1) block to all 16 peers ----
        if (t < L_ - 1 && tid < NCG) {
            push_block(sb, hn_off, HBAR_B, tid, c0);
        }
    }
    CLUSTER_SYNC();
}

// ---------------- launch ----------------
extern "C" void kernel_launch(void* const* d_in, const int* in_sizes, int n_in,
                              void* d_out, int out_size)
{
    const float* x  = (const float*)d_in[0];   // [32, 2048, 256]
    const float* h0 = (const float*)d_in[1];   // [32, 512]
    const float* Wz = (const float*)d_in[2];   // [512, 768]
    const float* Wr = (const float*)d_in[3];   // [512, 768]
    const float* Ww = (const float*)d_in[4];   // [512, 768]
    float* out = (float*)d_out;                // [2048, 32, 512]

    cudaFuncSetAttribute(gru_cluster_kernel,
                         cudaFuncAttributeMaxDynamicSharedMemorySize, SMEM_BYTES);
    cudaFuncSetAttribute(gru_cluster_kernel,
                         cudaFuncAttributeNonPortableClusterSizeAllowed, 1);

    dim3 pgrid(N3 / 128, (B_ * L_) / 128);     // (12, 512)
    precompute_x_kernel<<<pgrid, 256>>>(x, Wz, Wr, Ww);

    cudaLaunchConfig_t cfg = {};
    cfg.gridDim  = dim3(NCG, NBG, 1);          // 16 x 8 = 128 CTAs
    cfg.blockDim = dim3(NTHR, 1, 1);
    cfg.dynamicSmemBytes = SMEM_BYTES;
    cudaLaunchAttribute attrs[1];
    attrs[0].id = cudaLaunchAttributeClusterDimension;
    attrs[0].val.clusterDim.x = NCG;
    attrs[0].val.clusterDim.y = 1;
    attrs[0].val.clusterDim.z = 1;
    cfg.attrs = attrs;
    cfg.numAttrs = 1;
    cudaLaunchKernelEx(&cfg, gru_cluster_kernel, h0, Wz, Wr, Ww, out);
}

// round 7
// speedup vs baseline: 1.8263x; 1.8263x over previous
#include <cuda_runtime.h>
#include <cstdint>
#include <math.h>

typedef unsigned long long ull;

// Problem constants
#define B_    32
#define L_    2048
#define I_    256
#define H_    512
#define HX    768      // H + I
#define N3    1536     // 3*H (z | r | w)
#define NCG   16       // column groups (CTAs per batch group)
#define NBG   8        // batch groups
#define BPG   4        // batches per group
#define CPG   32       // gate columns per CTA per gate
#define NTHR  256

// ---------------- device scratch ----------------
__device__ float g_X[(size_t)L_ * B_ * N3];   // precomputed x-contributions
__device__ float g_rh[B_ * H_];               // r*h exchange
__device__ unsigned g_cnt[NBG * 32];          // per-group barrier counters (padded lines)
__device__ unsigned g_genv[NBG * 32];         // per-group barrier generations

// ---------------- smem layout (float offsets): weights only ----------------
#define WR_F 0                   // 32 x 512
#define WZ_F (32 * 512)
#define WW_F (64 * 512)
#define SM_FLOATS (96 * 512)
#define SMEM_BYTES (SM_FLOATS * 4)   // 196,608 B

// ---------------- asm helpers ----------------
__device__ __forceinline__ uint32_t smem_u32(const void* p) {
    uint32_t a;
    asm("{ .reg .u64 t; cvta.to.shared.u64 t, %1; cvt.u32.u64 %0, t; }" : "=r"(a) : "l"(p));
    return a;
}
__device__ __forceinline__ ull lds64(uint32_t a) {
    ull v;
    asm volatile("ld.shared.b64 %0, [%1];" : "=l"(v) : "r"(a));
    return v;
}
__device__ __forceinline__ ull ldg64cg(const void* p) {
    ull v;
    asm volatile("ld.global.cg.b64 %0, [%1];" : "=l"(v) : "l"(p));
    return v;
}
__device__ __forceinline__ void fma2(ull& acc, ull a, ull b) {
    asm volatile("fma.rn.f32x2 %0, %1, %2, %0;" : "+l"(acc) : "l"(a), "l"(b));
}
__device__ __forceinline__ float sum2(ull v) {
    float lo, hi;
    asm("mov.b64 {%0, %1}, %2;" : "=f"(lo), "=f"(hi) : "l"(v));
    return lo + hi;
}

// ---------------- barrier (arrive / wait split, tid0 poll) ----------------
__device__ __forceinline__ void bar_arrive(int bg, unsigned target) {
    __threadfence();
    unsigned* cnt = &g_cnt[bg * 32];
    unsigned* gen = &g_genv[bg * 32];
    if (atomicAdd(cnt, 1u) == (unsigned)(NCG - 1)) {
        *cnt = 0u;
        __threadfence();
        atomicExch(gen, target);
    }
}
__device__ __forceinline__ void bar_wait_all(int bg, unsigned target, int tid) {
    if (tid == 0) {
        unsigned* gen = &g_genv[bg * 32];
        unsigned v;
        do {
            asm volatile("ld.acquire.gpu.u32 %0, [%1];" : "=r"(v) : "l"(gen) : "memory");
        } while ((int)(v - target) < 0);
    }
    __syncthreads();
}

// ---------------- warp reduction: 16 chains over 32 lanes ----------------
// After return: thread pair (2l, 2l+1) holds chain o = (lane>>1)&15 in a[0].
__device__ __forceinline__ void reduce16(float a[16], int lane) {
#pragma unroll
    for (int o = 0; o < 8; o++) {
        bool hi = (lane & 16);
        float send = hi ? a[o] : a[o + 8];
        float keep = hi ? a[o + 8] : a[o];
        a[o] = keep + __shfl_xor_sync(0xffffffffu, send, 16);
    }
#pragma unroll
    for (int o = 0; o < 4; o++) {
        bool hi = (lane & 8);
        float send = hi ? a[o] : a[o + 4];
        float keep = hi ? a[o + 4] : a[o];
        a[o] = keep + __shfl_xor_sync(0xffffffffu, send, 8);
    }
#pragma unroll
    for (int o = 0; o < 2; o++) {
        bool hi = (lane & 4);
        float send = hi ? a[o] : a[o + 2];
        float keep = hi ? a[o + 2] : a[o];
        a[o] = keep + __shfl_xor_sync(0xffffffffu, send, 4);
    }
    {
        bool hi = (lane & 2);
        float send = hi ? a[0] : a[1];
        float keep = hi ? a[1] : a[0];
        a[0] = keep + __shfl_xor_sync(0xffffffffu, send, 2);
    }
    a[0] += __shfl_xor_sync(0xffffffffu, a[0], 1);
}

// ---------------- precompute GEMM: g_X = x . W[:,512:768]^T ----------------
__global__ void __launch_bounds__(256) precompute_x_kernel(
    const float* __restrict__ x,
    const float* __restrict__ Wz,
    const float* __restrict__ Wr,
    const float* __restrict__ Ww)
{
    __shared__ float As[16][132];
    __shared__ float Bs[16][132];

    const int m0 = blockIdx.y * 128;
    const int n0 = blockIdx.x * 128;
    const int tid = threadIdx.x;
    const int ty = tid >> 4;
    const int tx = tid & 15;

    float acc[8][8];
#pragma unroll
    for (int i = 0; i < 8; i++)
#pragma unroll
        for (int j = 0; j < 8; j++) acc[i][j] = 0.f;

    for (int k0 = 0; k0 < 256; k0 += 16) {
#pragma unroll
        for (int q = tid; q < 512; q += 256) {
            int r  = q >> 2;
            int kq = (q & 3) << 2;
            float4 v = *(const float4*)(x + (size_t)(m0 + r) * 256 + k0 + kq);
            As[kq + 0][r] = v.x; As[kq + 1][r] = v.y;
            As[kq + 2][r] = v.z; As[kq + 3][r] = v.w;
        }
#pragma unroll
        for (int q = tid; q < 512; q += 256) {
            int r  = q >> 2;
            int kq = (q & 3) << 2;
            int n  = n0 + r;
            const float* wrow;
            if (n < 512)        wrow = Wz + (size_t)n * HX;
            else if (n < 1024)  wrow = Wr + (size_t)(n - 512) * HX;
            else                wrow = Ww + (size_t)(n - 1024) * HX;
            float4 v = *(const float4*)(wrow + 512 + k0 + kq);
            Bs[kq + 0][r] = v.x; Bs[kq + 1][r] = v.y;
            Bs[kq + 2][r] = v.z; Bs[kq + 3][r] = v.w;
        }
        __syncthreads();
#pragma unroll
        for (int kk = 0; kk < 16; kk++) {
            float a[8], b[8];
#pragma unroll
            for (int i = 0; i < 8; i++) a[i] = As[kk][ty * 8 + i];
#pragma unroll
            for (int j = 0; j < 8; j++) b[j] = Bs[kk][tx * 8 + j];
#pragma unroll
            for (int i = 0; i < 8; i++)
#pragma unroll
                for (int j = 0; j < 8; j++) acc[i][j] += a[i] * b[j];
        }
        __syncthreads();
    }

#pragma unroll
    for (int i = 0; i < 8; i++) {
        int m = m0 + ty * 8 + i;
        int t = m & 2047;
        int b = m >> 11;
        size_t base = ((size_t)t * B_ + b) * N3 + n0 + tx * 8;
        *(float4*)&g_X[base + 0] = make_float4(acc[i][0], acc[i][1], acc[i][2], acc[i][3]);
        *(float4*)&g_X[base + 4] = make_float4(acc[i][4], acc[i][5], acc[i][6], acc[i][7]);
    }
}

// ---------------- persistent recurrent kernel ----------------
__global__ void __launch_bounds__(NTHR, 1) gru_persistent_kernel(
    const float* __restrict__ h0,
    const float* __restrict__ Wz,
    const float* __restrict__ Wr,
    const float* __restrict__ Ww,
    float* __restrict__ out)
{
    extern __shared__ float sm[];
    const uint32_t sb = smem_u32(sm);
    const int tid  = threadIdx.x;
    const int wg   = tid >> 5;
    const int lane = tid & 31;
    const int cta  = blockIdx.x;
    const int cg   = cta & (NCG - 1);
    const int bg   = cta >> 4;
    const int b0   = bg * BPG;
    const int c0   = cg * CPG;

    // ---- cache weight h-parts: 3 x [32 rows x 512] ----
    for (int q = tid; q < 32 * 128; q += NTHR) {
        int row = q >> 7, f4 = q & 127;
        ((float4*)(sm + WR_F))[row * 128 + f4] = *(const float4*)(Wr + (size_t)(c0 + row) * HX + f4 * 4);
        ((float4*)(sm + WZ_F))[row * 128 + f4] = *(const float4*)(Wz + (size_t)(c0 + row) * HX + f4 * 4);
        ((float4*)(sm + WW_F))[row * 128 + f4] = *(const float4*)(Ww + (size_t)(c0 + row) * HX + f4 * 4);
    }
    __syncthreads();

    unsigned gen0;
    asm volatile("ld.acquire.gpu.u32 %0, [%1];" : "=r"(gen0) : "l"(&g_genv[bg * 32]) : "memory");

    // output mapping: even lanes own output o = (lane>>1)&15 = c*4+b
    const int o   = (lane >> 1) & 15;
    const int oc  = o >> 2;              // col within warp's 4
    const int ob  = o & 3;               // batch within group
    const int colg = c0 + wg * 4 + oc;   // global gate column (0..511)
    const bool wr = !(lane & 1);

    // prefetch x-contributions for t=0
    size_t xbase = ((size_t)0 * B_ + b0 + ob) * N3;
    float xz = __ldg(&g_X[xbase + colg]);
    float xr = __ldg(&g_X[xbase + 512 + colg]);
    float xw = __ldg(&g_X[xbase + 1024 + colg]);

    for (int t = 0; t < L_; t++) {
        const float* hsrc = (t == 0) ? h0 : (out + (size_t)(t - 1) * B_ * H_);

        // ---- load h(t) slice directly into registers (L2, coalesced) ----
        ull hb[4][8];
#pragma unroll
        for (int b = 0; b < 4; b++)
#pragma unroll
            for (int i = 0; i < 8; i++)
                hb[b][i] = ldg64cg(hsrc + (size_t)(b0 + b) * H_ + (i * 32 + lane) * 2);
        float hval;
        {
            float v;
            asm volatile("ld.global.cg.f32 %0, [%1];" : "=f"(v)
                         : "l"(hsrc + (size_t)(b0 + ob) * H_ + colg));
            hval = v;
        }

        // ================= r gate =================
        {
            ull acc[4][4];
#pragma unroll
            for (int c = 0; c < 4; c++)
#pragma unroll
                for (int b = 0; b < 4; b++) acc[c][b] = 0ull;

            const uint32_t wb = sb + (WR_F + (wg * 4) * 512) * 4;
#pragma unroll
            for (int i = 0; i < 8; i++) {
                uint32_t off = (uint32_t)(i * 32 + lane) * 8u;
#pragma unroll
                for (int c = 0; c < 4; c++) {
                    ull wv = lds64(wb + c * 2048 + off);
                    fma2(acc[c][0], hb[0][i], wv);
                    fma2(acc[c][1], hb[1][i], wv);
                    fma2(acc[c][2], hb[2][i], wv);
                    fma2(acc[c][3], hb[3][i], wv);
                }
            }
            float a[16];
#pragma unroll
            for (int c = 0; c < 4; c++)
#pragma unroll
                for (int b = 0; b < 4; b++) a[c * 4 + b] = sum2(acc[c][b]);
            reduce16(a, lane);

            if (wr) {
                float r = 1.f / (1.f + __expf(-(a[0] + xr)));
                __stcg(&g_rh[(size_t)(b0 + ob) * H_ + colg], r * hval);
            }
        }
        __syncthreads();
        if (tid == 0) bar_arrive(bg, gen0 + (unsigned)(2 * t + 1));

        // ================= z gate (overlaps barrier A propagation) =================
        float zv;
        {
            ull acc[4][4];
#pragma unroll
            for (int c = 0; c < 4; c++)
#pragma unroll
                for (int b = 0; b < 4; b++) acc[c][b] = 0ull;

            const uint32_t wb = sb + (WZ_F + (wg * 4) * 512) * 4;
#pragma unroll
            for (int i = 0; i < 8; i++) {
                uint32_t off = (uint32_t)(i * 32 + lane) * 8u;
#pragma unroll
                for (int c = 0; c < 4; c++) {
                    ull wv = lds64(wb + c * 2048 + off);
                    fma2(acc[c][0], hb[0][i], wv);
                    fma2(acc[c][1], hb[1][i], wv);
                    fma2(acc[c][2], hb[2][i], wv);
                    fma2(acc[c][3], hb[3][i], wv);
                }
            }
            float a[16];
#pragma unroll
            for (int c = 0; c < 4; c++)
#pragma unroll
                for (int b = 0; b < 4; b++) a[c * 4 + b] = sum2(acc[c][b]);
            reduce16(a, lane);
            zv = 1.f / (1.f + __expf(-(a[0] + xz)));
        }

        // ---- wait for all r*h in group, then read it directly into registers ----
        bar_wait_all(bg, gen0 + (unsigned)(2 * t + 1), tid);
        ull rb[4][8];
#pragma unroll
        for (int b = 0; b < 4; b++)
#pragma unroll
            for (int i = 0; i < 8; i++)
                rb[b][i] = ldg64cg(g_rh + (size_t)(b0 + b) * H_ + (i * 32 + lane) * 2);

        // ================= w gate (candidate) + blend =================
        {
            ull acc[4][4];
#pragma unroll
            for (int c = 0; c < 4; c++)
#pragma unroll
                for (int b = 0; b < 4; b++) acc[c][b] = 0ull;

            const uint32_t wb = sb + (WW_F + (wg * 4) * 512) * 4;
#pragma unroll
            for (int i = 0; i < 8; i++) {
                uint32_t off = (uint32_t)(i * 32 + lane) * 8u;
#pragma unroll
                for (int c = 0; c < 4; c++) {
                    ull wv = lds64(wb + c * 2048 + off);
                    fma2(acc[c][0], rb[0][i], wv);
                    fma2(acc[c][1], rb[1][i], wv);
                    fma2(acc[c][2], rb[2][i], wv);
                    fma2(acc[c][3], rb[3][i], wv);
                }
            }
            float a[16];
#pragma unroll
            for (int c = 0; c < 4; c++)
#pragma unroll
                for (int b = 0; b < 4; b++) a[c * 4 + b] = sum2(acc[c][b]);
            reduce16(a, lane);

            if (wr) {
                float hh = tanhf(a[0] + xw);
                float hn = hval + zv * (hh - hval);
                __stcg(&out[((size_t)t * B_ + b0 + ob) * H_ + colg], hn);
            }
        }

        // ---- prefetch x-contributions for t+1 (independent of barrier) ----
        {
            int tn = (t + 1 < L_) ? (t + 1) : t;
            xbase = ((size_t)tn * B_ + b0 + ob) * N3;
            xz = __ldg(&g_X[xbase + colg]);
            xr = __ldg(&g_X[xbase + 512 + colg]);
            xw = __ldg(&g_X[xbase + 1024 + colg]);
        }

        __syncthreads();
        if (tid == 0) bar_arrive(bg, gen0 + (unsigned)(2 * t + 2));
        bar_wait_all(bg, gen0 + (unsigned)(2 * t + 2), tid);
    }
}

// ---------------- launch ----------------
extern "C" void kernel_launch(void* const* d_in, const int* in_sizes, int n_in,
                              void* d_out, int out_size)
{
    const float* x  = (const float*)d_in[0];   // [32, 2048, 256]
    const float* h0 = (const float*)d_in[1];   // [32, 512]
    const float* Wz = (const float*)d_in[2];   // [512, 768]
    const float* Wr = (const float*)d_in[3];   // [512, 768]
    const float* Ww = (const float*)d_in[4];   // [512, 768]
    float* out = (float*)d_out;                // [2048, 32, 512]

    cudaFuncSetAttribute(gru_persistent_kernel,
                         cudaFuncAttributeMaxDynamicSharedMemorySize, SMEM_BYTES);

    dim3 pgrid(N3 / 128, (B_ * L_) / 128);     // (12, 512)
    precompute_x_kernel<<<pgrid, 256>>>(x, Wz, Wr, Ww);

    gru_persistent_kernel<<<NCG * NBG, NTHR, SMEM_BYTES>>>(h0, Wz, Wr, Ww, out);
}